// round 7
// baseline (speedup 1.0000x reference)
#include <cuda_runtime.h>
#include <cstdint>

#define N_NODES 100000
#define N_EDGES 600000
#define F_IN    128
#define F_OUT   64
#define CAP     64          // bucket capacity per node (P(deg>=64) ~ 1e-40 for Poisson(6))

typedef unsigned long long ull;

// ---------------- device scratch (static globals; no allocation) ----------------
__device__ float g_inv_sigma;
__device__ float g_deg[N_NODES];
__device__ int   g_cur[N_NODES];
__device__ int2  g_bkt[(size_t)N_NODES * CAP];    // (row, float_bits(w)) per slot
__device__ float g_xp[(size_t)N_NODES * F_OUT];   // 25.6 MB, mostly L2-resident

__device__ __forceinline__ ull pack2(float lo, float hi) {
    ull r;
    asm("mov.b64 %0, {%1, %2};" : "=l"(r) : "f"(lo), "f"(hi));
    return r;
}
__device__ __forceinline__ void unpack2(ull v, float& lo, float& hi) {
    asm("mov.b64 {%0, %1}, %2;" : "=f"(lo), "=f"(hi) : "l"(v));
}
__device__ __forceinline__ ull ffma2(ull a, ull b, ull c) {
    ull d;
    asm("fma.rn.f32x2 %0, %1, %2, %3;" : "=l"(d) : "l"(a), "l"(b), "l"(c));
    return d;
}

// ------------- 1) sigma (block 0) + deg/cur init (blocks 1..) -------------------
__global__ void k_sigma_init(const float* __restrict__ W, const float* __restrict__ u, int n) {
    if (blockIdx.x == 0) {
        __shared__ float us[F_IN];
        __shared__ float v[F_OUT];
        __shared__ float wv[F_IN];
        __shared__ float s_inv;
        int t = threadIdx.x;
        if (t < F_IN) us[t] = u[t];
        __syncthreads();
        if (t < F_OUT) {
            float s = 0.f;
            #pragma unroll 4
            for (int i = 0; i < F_IN; i++) s += W[i * F_OUT + t] * us[i];
            v[t] = s;
        }
        __syncthreads();
        if (t == 0) {
            float nn = 0.f;
            for (int j = 0; j < F_OUT; j++) nn += v[j] * v[j];
            s_inv = 1.0f / (sqrtf(nn) + 1e-12f);
        }
        __syncthreads();
        if (t < F_IN) {
            float inv = s_inv;
            float s = 0.f;
            const float* Wr = W + t * F_OUT;
            #pragma unroll 4
            for (int j = 0; j < F_OUT; j++) s += Wr[j] * (v[j] * inv);
            wv[t] = s;
        }
        __syncthreads();
        if (t == 0) {
            float nn = 0.f;
            for (int i = 0; i < F_IN; i++) nn += wv[i] * wv[i];
            float nw = sqrtf(nn);
            float sigma = nn / (nw + 1e-12f);   // u2.(Wv), u2 = wv/(||wv||+eps)
            g_inv_sigma = 1.0f / sigma;
        }
    } else {
        int i = (blockIdx.x - 1) * blockDim.x + threadIdx.x;
        if (i < n) {
            g_deg[i] = 1.0f;    // self-loop
            g_cur[i] = 0;
        }
    }
}

// ------------- 2) fused GEMM (blocks [0, gemmBlocks)) + edges (rest) -------------
// GEMM: 128 rows x 64 cols per block, 256 threads, FFMA2 inner loop.
// Edges: sigmoid + degree atomic + bucket fill, 256 edges per block.
__global__ __launch_bounds__(256) void k_gemm_edges(
    const float* __restrict__ x, const float* __restrict__ W,
    const float* __restrict__ ew, const int* __restrict__ ei,
    int n, int E, int gemmBlocks)
{
    __shared__ float xs[16][128];   // [kk][row], transposed
    __shared__ ull   ws2[16][64];   // [kk][col], W value duplicated as packed f32x2

    if (blockIdx.x >= gemmBlocks) {
        // ---------------- edge path ----------------
        int e = (blockIdx.x - gemmBlocks) * blockDim.x + threadIdx.x;
        if (e >= E) return;
        float w = 1.0f / (1.0f + __expf(-ew[e]));
        int r = ei[e];
        int c = ei[E + e];
        if ((unsigned)r >= (unsigned)N_NODES || (unsigned)c >= (unsigned)N_NODES) return;
        atomicAdd(&g_deg[c], w);
        int pos = atomicAdd(&g_cur[c], 1);
        if (pos < CAP)
            g_bkt[(size_t)c * CAP + pos] = make_int2(r, __float_as_int(w));
        return;
    }

    // ---------------- gemm path ----------------
    int t  = threadIdx.x;
    int tx = t & 15;
    int ty = t >> 4;
    int rowBase = blockIdx.x * 128;
    float invs = g_inv_sigma;

    ull acc2[4][4];                 // [row-pair][col], packed f32x2 (even,odd row)
    #pragma unroll
    for (int rp = 0; rp < 4; rp++)
        #pragma unroll
        for (int c = 0; c < 4; c++) acc2[rp][c] = 0ull;

    for (int k0 = 0; k0 < F_IN; k0 += 16) {
        #pragma unroll
        for (int s = 0; s < 2; s++) {
            int f   = t + s * 256;
            int row = f >> 2;
            int seg = f & 3;
            int gr  = rowBase + row;
            float4 val = make_float4(0.f, 0.f, 0.f, 0.f);
            if (gr < n) val = *(const float4*)(x + (size_t)gr * F_IN + k0 + seg * 4);
            xs[seg * 4 + 0][row] = val.x;
            xs[seg * 4 + 1][row] = val.y;
            xs[seg * 4 + 2][row] = val.z;
            xs[seg * 4 + 3][row] = val.w;
        }
        {
            int col4 = t & 15;
            int kk   = t >> 4;
            float4 wv = *(const float4*)(W + (size_t)(k0 + kk) * F_OUT + col4 * 4);
            wv.x *= invs; wv.y *= invs; wv.z *= invs; wv.w *= invs;
            ws2[kk][col4 * 4 + 0] = pack2(wv.x, wv.x);
            ws2[kk][col4 * 4 + 1] = pack2(wv.y, wv.y);
            ws2[kk][col4 * 4 + 2] = pack2(wv.z, wv.z);
            ws2[kk][col4 * 4 + 3] = pack2(wv.w, wv.w);
        }
        __syncthreads();
        #pragma unroll
        for (int kk = 0; kk < 16; kk++) {
            float4 a0 = *(const float4*)&xs[kk][ty * 8];
            float4 a1 = *(const float4*)&xs[kk][ty * 8 + 4];
            ull ap[4];
            ap[0] = pack2(a0.x, a0.y);
            ap[1] = pack2(a0.z, a0.w);
            ap[2] = pack2(a1.x, a1.y);
            ap[3] = pack2(a1.z, a1.w);
            ull bb0 = ws2[kk][tx * 4 + 0];
            ull bb1 = ws2[kk][tx * 4 + 1];
            ull bb2 = ws2[kk][tx * 4 + 2];
            ull bb3 = ws2[kk][tx * 4 + 3];
            #pragma unroll
            for (int rp = 0; rp < 4; rp++) {
                acc2[rp][0] = ffma2(ap[rp], bb0, acc2[rp][0]);
                acc2[rp][1] = ffma2(ap[rp], bb1, acc2[rp][1]);
                acc2[rp][2] = ffma2(ap[rp], bb2, acc2[rp][2]);
                acc2[rp][3] = ffma2(ap[rp], bb3, acc2[rp][3]);
            }
        }
        __syncthreads();
    }

    #pragma unroll
    for (int rp = 0; rp < 4; rp++) {
        float e0, o0, e1, o1, e2, o2, e3, o3;
        unpack2(acc2[rp][0], e0, o0);
        unpack2(acc2[rp][1], e1, o1);
        unpack2(acc2[rp][2], e2, o2);
        unpack2(acc2[rp][3], e3, o3);
        int gr0 = rowBase + ty * 8 + rp * 2;
        if (gr0 < n)
            *(float4*)(g_xp + (size_t)gr0 * F_OUT + tx * 4) = make_float4(e0, e1, e2, e3);
        if (gr0 + 1 < n)
            *(float4*)(g_xp + (size_t)(gr0 + 1) * F_OUT + tx * 4) = make_float4(o0, o1, o2, o3);
    }
}

// ------------- 3) aggregation (gather, atomic-free) -----------------------------
// Half-warp (16 lanes x float4) per node:
//   out[c] = sum_e rsqrt(deg[r])*w*rsqrt(deg[c]) * xp[r]  +  xp[c]/deg[c]  +  bias
__global__ __launch_bounds__(256) void k_agg(
    const float* __restrict__ bias, float* __restrict__ out, int n)
{
    int gt   = blockIdx.x * 256 + threadIdx.x;
    int node = gt >> 4;
    int l    = gt & 15;
    if (node >= n) return;

    float degc  = g_deg[node];
    float dis_c = rsqrtf(degc);
    int cnt = g_cur[node];
    if (cnt > CAP) cnt = CAP;
    const int2* bk = g_bkt + (size_t)node * CAP;

    float4 acc = make_float4(0.f, 0.f, 0.f, 0.f);
    if (cnt > 0) {
        int2 cu = bk[0];           // software pipeline: index/weight one ahead
        for (int e = 0; e < cnt; e++) {
            int   r = cu.x;
            float w = __int_as_float(cu.y);
            if (e + 1 < cnt) cu = bk[e + 1];
            float ne = rsqrtf(g_deg[r]) * w * dis_c;
            float4 xv = *(const float4*)(g_xp + (size_t)r * F_OUT + l * 4);
            acc.x += ne * xv.x;
            acc.y += ne * xv.y;
            acc.z += ne * xv.z;
            acc.w += ne * xv.w;
        }
    }
    float invdeg = 1.0f / degc;
    float4 self = *(const float4*)(g_xp + (size_t)node * F_OUT + l * 4);
    float4 b4   = ((const float4*)bias)[l];
    float4 o;
    o.x = acc.x + self.x * invdeg + b4.x;
    o.y = acc.y + self.y * invdeg + b4.y;
    o.z = acc.z + self.z * invdeg + b4.z;
    o.w = acc.w + self.w * invdeg + b4.w;
    *(float4*)(out + (size_t)node * F_OUT + l * 4) = o;
}

// ---------------------------------- launch --------------------------------------
extern "C" void kernel_launch(void* const* d_in, const int* in_sizes, int n_in,
                              void* d_out, int out_size) {
    const float* x    = (const float*)d_in[0];
    const int*   ei   = (const int*)d_in[1];    // int32 (JAX default, no x64)
    const float* W    = (const float*)d_in[2];
    const float* bias = (const float*)d_in[3];
    const float* ew   = (const float*)d_in[4];
    const float* u    = (const float*)d_in[5];
    float* out = (float*)d_out;

    int N = in_sizes[0] / F_IN;
    int E = in_sizes[4];

    int gemmBlocks = (N + 127) / 128;
    int edgeBlocks = (E + 255) / 256;

    k_sigma_init<<<(N + 255) / 256 + 1, 256>>>(W, u, N);
    k_gemm_edges<<<gemmBlocks + edgeBlocks, 256>>>(x, W, ew, ei, N, E, gemmBlocks);
    {
        long long total = (long long)N * 16;
        int blocks = (int)((total + 255) / 256);
        k_agg<<<blocks, 256>>>(bias, out, N);
    }
}

// round 9
// speedup vs baseline: 1.2463x; 1.2463x over previous
#include <cuda_runtime.h>
#include <cstdint>

#define N_NODES 100000
#define N_EDGES 600000
#define F_IN    128
#define F_OUT   64
#define CAP     64          // bucket capacity per node (P(deg>=64) ~ 1e-40 for Poisson(6))

typedef unsigned long long ull;

// ---------------- device scratch (static globals; no allocation) ----------------
__device__ float g_inv_sigma;
__device__ float g_deg[N_NODES];
__device__ int   g_cur[N_NODES];
__device__ int2  g_bkt[(size_t)N_NODES * CAP];    // (row, float_bits(w)) per slot
__device__ float g_xp[(size_t)N_NODES * F_OUT];   // 25.6 MB, mostly L2-resident

__device__ __forceinline__ ull pack2(float lo, float hi) {
    ull r;
    asm("mov.b64 %0, {%1, %2};" : "=l"(r) : "f"(lo), "f"(hi));
    return r;
}
__device__ __forceinline__ void unpack2(ull v, float& lo, float& hi) {
    asm("mov.b64 {%0, %1}, %2;" : "=f"(lo), "=f"(hi) : "l"(v));
}
__device__ __forceinline__ ull ffma2(ull a, ull b, ull c) {
    ull d;
    asm("fma.rn.f32x2 %0, %1, %2, %3;" : "=l"(d) : "l"(a), "l"(b), "l"(c));
    return d;
}

// ------------- 1) sigma (block 0, W staged to smem) + deg/cur init --------------
__global__ void k_sigma_init(const float* __restrict__ W, const float* __restrict__ u, int n) {
    if (blockIdx.x == 0) {
        __shared__ float Wsh[F_IN * F_OUT];   // 32 KB
        __shared__ float us[F_IN];
        __shared__ float v[F_OUT];
        __shared__ float wv[F_IN];
        __shared__ float s_inv;
        int t = threadIdx.x;   // 256 threads
        // stage W with high MLP: 2048 float4 over 256 threads = 8 each
        #pragma unroll
        for (int i = 0; i < (F_IN * F_OUT) / 4 / 256; i++) {
            int idx = t + i * 256;
            ((float4*)Wsh)[idx] = ((const float4*)W)[idx];
        }
        if (t < F_IN) us[t] = u[t];
        __syncthreads();
        if (t < F_OUT) {
            float s = 0.f;
            #pragma unroll 8
            for (int i = 0; i < F_IN; i++) s += Wsh[i * F_OUT + t] * us[i];
            v[t] = s;
        }
        __syncthreads();
        if (t == 0) {
            float nn = 0.f;
            #pragma unroll 8
            for (int j = 0; j < F_OUT; j++) nn += v[j] * v[j];
            s_inv = 1.0f / (sqrtf(nn) + 1e-12f);
        }
        __syncthreads();
        if (t < F_IN) {
            float inv = s_inv;
            float s = 0.f;
            const float* Wr = Wsh + t * F_OUT;
            #pragma unroll 8
            for (int j = 0; j < F_OUT; j++) s += Wr[j] * (v[j] * inv);
            wv[t] = s;
        }
        __syncthreads();
        if (t == 0) {
            float nn = 0.f;
            #pragma unroll 8
            for (int i = 0; i < F_IN; i++) nn += wv[i] * wv[i];
            float nw = sqrtf(nn);
            float sigma = nn / (nw + 1e-12f);   // u2.(Wv), u2 = wv/(||wv||+eps)
            g_inv_sigma = 1.0f / sigma;
        }
    } else {
        int i = (blockIdx.x - 1) * blockDim.x + threadIdx.x;
        if (i < n) {
            g_deg[i] = 1.0f;    // self-loop
            g_cur[i] = 0;
        }
    }
}

// ------------- 2) edges: sigmoid + degree atomic + bucket fill ------------------
__global__ __launch_bounds__(256) void k_edges(
    const float* __restrict__ ew, const int* __restrict__ ei, int E)
{
    int e = blockIdx.x * blockDim.x + threadIdx.x;
    if (e >= E) return;
    float w = 1.0f / (1.0f + __expf(-ew[e]));
    int r = ei[e];
    int c = ei[E + e];
    if ((unsigned)r >= (unsigned)N_NODES || (unsigned)c >= (unsigned)N_NODES) return;
    atomicAdd(&g_deg[c], w);
    int pos = atomicAdd(&g_cur[c], 1);
    if (pos < CAP)
        g_bkt[(size_t)c * CAP + pos] = make_int2(r, __float_as_int(w));
}

// ------------- 3) GEMM xp = x @ (W/sigma), FFMA2 inner loop ---------------------
// Tile: 128 rows x 64 cols per block, 256 threads, 8x4 micro-tile as 4 row-pairs.
__global__ __launch_bounds__(256) void k_gemm(
    const float* __restrict__ x, const float* __restrict__ W, int n)
{
    __shared__ float xs[16][128];   // [kk][row], transposed
    __shared__ float ws[16][64];    // [kk][col]
    int t  = threadIdx.x;
    int tx = t & 15;
    int ty = t >> 4;
    int rowBase = blockIdx.x * 128;
    float invs = g_inv_sigma;

    ull acc2[4][4];                 // [row-pair][col], packed f32x2 (even,odd row)
    #pragma unroll
    for (int rp = 0; rp < 4; rp++)
        #pragma unroll
        for (int c = 0; c < 4; c++) acc2[rp][c] = 0ull;

    for (int k0 = 0; k0 < F_IN; k0 += 16) {
        #pragma unroll
        for (int s = 0; s < 2; s++) {
            int f   = t + s * 256;
            int row = f >> 2;
            int seg = f & 3;
            int gr  = rowBase + row;
            float4 val = make_float4(0.f, 0.f, 0.f, 0.f);
            if (gr < n) val = *(const float4*)(x + (size_t)gr * F_IN + k0 + seg * 4);
            xs[seg * 4 + 0][row] = val.x;
            xs[seg * 4 + 1][row] = val.y;
            xs[seg * 4 + 2][row] = val.z;
            xs[seg * 4 + 3][row] = val.w;
        }
        {
            int col4 = t & 15;
            int kk   = t >> 4;
            float4 wv = *(const float4*)(W + (size_t)(k0 + kk) * F_OUT + col4 * 4);
            wv.x *= invs; wv.y *= invs; wv.z *= invs; wv.w *= invs;
            *(float4*)&ws[kk][col4 * 4] = wv;
        }
        __syncthreads();
        #pragma unroll
        for (int kk = 0; kk < 16; kk++) {
            float4 a0 = *(const float4*)&xs[kk][ty * 8];
            float4 a1 = *(const float4*)&xs[kk][ty * 8 + 4];
            float4 b  = *(const float4*)&ws[kk][tx * 4];
            ull ap[4];
            ap[0] = pack2(a0.x, a0.y);
            ap[1] = pack2(a0.z, a0.w);
            ap[2] = pack2(a1.x, a1.y);
            ap[3] = pack2(a1.z, a1.w);
            ull bb[4];
            bb[0] = pack2(b.x, b.x);
            bb[1] = pack2(b.y, b.y);
            bb[2] = pack2(b.z, b.z);
            bb[3] = pack2(b.w, b.w);
            #pragma unroll
            for (int rp = 0; rp < 4; rp++) {
                acc2[rp][0] = ffma2(ap[rp], bb[0], acc2[rp][0]);
                acc2[rp][1] = ffma2(ap[rp], bb[1], acc2[rp][1]);
                acc2[rp][2] = ffma2(ap[rp], bb[2], acc2[rp][2]);
                acc2[rp][3] = ffma2(ap[rp], bb[3], acc2[rp][3]);
            }
        }
        __syncthreads();
    }

    #pragma unroll
    for (int rp = 0; rp < 4; rp++) {
        float e0, o0, e1, o1, e2, o2, e3, o3;
        unpack2(acc2[rp][0], e0, o0);
        unpack2(acc2[rp][1], e1, o1);
        unpack2(acc2[rp][2], e2, o2);
        unpack2(acc2[rp][3], e3, o3);
        int gr0 = rowBase + ty * 8 + rp * 2;
        if (gr0 < n)
            *(float4*)(g_xp + (size_t)gr0 * F_OUT + tx * 4) = make_float4(e0, e1, e2, e3);
        if (gr0 + 1 < n)
            *(float4*)(g_xp + (size_t)(gr0 + 1) * F_OUT + tx * 4) = make_float4(o0, o1, o2, o3);
    }
}

// ------------- 4) aggregation (gather, atomic-free) -----------------------------
// Half-warp (16 lanes x float4) per node:
//   out[c] = sum_e rsqrt(deg[r])*w*rsqrt(deg[c]) * xp[r]  +  xp[c]/deg[c]  +  bias
__global__ __launch_bounds__(256) void k_agg(
    const float* __restrict__ bias, float* __restrict__ out, int n)
{
    int gt   = blockIdx.x * 256 + threadIdx.x;
    int node = gt >> 4;
    int l    = gt & 15;
    if (node >= n) return;

    float degc  = g_deg[node];
    float dis_c = rsqrtf(degc);
    int cnt = g_cur[node];
    if (cnt > CAP) cnt = CAP;
    const int2* bk = g_bkt + (size_t)node * CAP;

    float4 acc = make_float4(0.f, 0.f, 0.f, 0.f);
    if (cnt > 0) {
        int2 cu = bk[0];           // software pipeline: index/weight one ahead
        for (int e = 0; e < cnt; e++) {
            int   r = cu.x;
            float w = __int_as_float(cu.y);
            if (e + 1 < cnt) cu = bk[e + 1];
            float ne = rsqrtf(g_deg[r]) * w * dis_c;
            float4 xv = *(const float4*)(g_xp + (size_t)r * F_OUT + l * 4);
            acc.x += ne * xv.x;
            acc.y += ne * xv.y;
            acc.z += ne * xv.z;
            acc.w += ne * xv.w;
        }
    }
    float invdeg = 1.0f / degc;
    float4 self = *(const float4*)(g_xp + (size_t)node * F_OUT + l * 4);
    float4 b4   = ((const float4*)bias)[l];
    float4 o;
    o.x = acc.x + self.x * invdeg + b4.x;
    o.y = acc.y + self.y * invdeg + b4.y;
    o.z = acc.z + self.z * invdeg + b4.z;
    o.w = acc.w + self.w * invdeg + b4.w;
    *(float4*)(out + (size_t)node * F_OUT + l * 4) = o;
}

// ---------------------------------- launch --------------------------------------
extern "C" void kernel_launch(void* const* d_in, const int* in_sizes, int n_in,
                              void* d_out, int out_size) {
    const float* x    = (const float*)d_in[0];
    const int*   ei   = (const int*)d_in[1];    // int32 (JAX default, no x64)
    const float* W    = (const float*)d_in[2];
    const float* bias = (const float*)d_in[3];
    const float* ew   = (const float*)d_in[4];
    const float* u    = (const float*)d_in[5];
    float* out = (float*)d_out;

    int N = in_sizes[0] / F_IN;
    int E = in_sizes[4];

    k_sigma_init<<<(N + 255) / 256 + 1, 256>>>(W, u, N);
    k_edges<<<(E + 255) / 256, 256>>>(ew, ei, E);
    k_gemm<<<(N + 127) / 128, 256>>>(x, W, N);
    {
        long long total = (long long)N * 16;
        int blocks = (int)((total + 255) / 256);
        k_agg<<<blocks, 256>>>(bias, out, N);
    }
}

// round 11
// speedup vs baseline: 1.2487x; 1.0019x over previous
#include <cuda_runtime.h>
#include <cstdint>

#define N_NODES 100000
#define N_EDGES 600000
#define F_IN    128
#define F_OUT   64
#define CAP     64          // bucket capacity per node (P(deg>=64) ~ 1e-40 for Poisson(6))

typedef unsigned long long ull;

// ---------------- device scratch (static globals; no allocation) ----------------
__device__ float g_inv_sigma;
__device__ float g_deg[N_NODES];
__device__ int   g_cur[N_NODES];
__device__ int2  g_bkt[(size_t)N_NODES * CAP];    // (row, float_bits(w)) per slot
__device__ float g_xp[(size_t)N_NODES * F_OUT];   // 25.6 MB, mostly L2-resident

__device__ __forceinline__ ull pack2(float lo, float hi) {
    ull r;
    asm("mov.b64 %0, {%1, %2};" : "=l"(r) : "f"(lo), "f"(hi));
    return r;
}
__device__ __forceinline__ void unpack2(ull v, float& lo, float& hi) {
    asm("mov.b64 {%0, %1}, %2;" : "=f"(lo), "=f"(hi) : "l"(v));
}
__device__ __forceinline__ ull ffma2(ull a, ull b, ull c) {
    ull d;
    asm("fma.rn.f32x2 %0, %1, %2, %3;" : "=l"(d) : "l"(a), "l"(b), "l"(c));
    return d;
}

// ------------- 1) sigma (block 0, W staged to smem) + deg/cur init --------------
__global__ void k_sigma_init(const float* __restrict__ W, const float* __restrict__ u, int n) {
    if (blockIdx.x == 0) {
        __shared__ float Wsh[F_IN * F_OUT];   // 32 KB
        __shared__ float us[F_IN];
        __shared__ float v[F_OUT];
        __shared__ float wv[F_IN];
        __shared__ float s_inv;
        int t = threadIdx.x;   // 256 threads
        #pragma unroll
        for (int i = 0; i < (F_IN * F_OUT) / 4 / 256; i++) {
            int idx = t + i * 256;
            ((float4*)Wsh)[idx] = ((const float4*)W)[idx];
        }
        if (t < F_IN) us[t] = u[t];
        __syncthreads();
        if (t < F_OUT) {
            float s = 0.f;
            #pragma unroll 8
            for (int i = 0; i < F_IN; i++) s += Wsh[i * F_OUT + t] * us[i];
            v[t] = s;
        }
        __syncthreads();
        if (t == 0) {
            float nn = 0.f;
            #pragma unroll 8
            for (int j = 0; j < F_OUT; j++) nn += v[j] * v[j];
            s_inv = 1.0f / (sqrtf(nn) + 1e-12f);
        }
        __syncthreads();
        if (t < F_IN) {
            float inv = s_inv;
            float s = 0.f;
            const float* Wr = Wsh + t * F_OUT;
            #pragma unroll 8
            for (int j = 0; j < F_OUT; j++) s += Wr[j] * (v[j] * inv);
            wv[t] = s;
        }
        __syncthreads();
        if (t == 0) {
            float nn = 0.f;
            #pragma unroll 8
            for (int i = 0; i < F_IN; i++) nn += wv[i] * wv[i];
            float nw = sqrtf(nn);
            float sigma = nn / (nw + 1e-12f);   // u2.(Wv), u2 = wv/(||wv||+eps)
            g_inv_sigma = 1.0f / sigma;
        }
    } else {
        int i = (blockIdx.x - 1) * blockDim.x + threadIdx.x;
        if (i < n) {
            g_deg[i] = 1.0f;    // self-loop
            g_cur[i] = 0;
        }
    }
}

// ------------- 2) edges: sigmoid + degree atomic + bucket fill ------------------
__global__ __launch_bounds__(256) void k_edges(
    const float* __restrict__ ew, const int* __restrict__ ei, int E)
{
    int e = blockIdx.x * blockDim.x + threadIdx.x;
    if (e >= E) return;
    float w = 1.0f / (1.0f + __expf(-ew[e]));
    int r = ei[e];
    int c = ei[E + e];
    if ((unsigned)r >= (unsigned)N_NODES || (unsigned)c >= (unsigned)N_NODES) return;
    atomicAdd(&g_deg[c], w);
    int pos = atomicAdd(&g_cur[c], 1);
    if (pos < CAP)
        g_bkt[(size_t)c * CAP + pos] = make_int2(r, __float_as_int(w));
}

// ------------- 3) GEMM xp = x @ (W/sigma), FFMA2 inner loop ---------------------
// Tile: 128 rows x 64 cols per block, 256 threads, 8x4 micro-tile as 4 row-pairs.
__global__ __launch_bounds__(256) void k_gemm(
    const float* __restrict__ x, const float* __restrict__ W, int n)
{
    __shared__ float xs[16][128];   // [kk][row], transposed; adjacent rows = f32x2 pair
    __shared__ float ws[16][64];    // [kk][col]
    int t  = threadIdx.x;
    int tx = t & 15;
    int ty = t >> 4;
    int rowBase = blockIdx.x * 128;
    float invs = g_inv_sigma;

    ull acc2[4][4];                 // [row-pair][col], packed f32x2 (even,odd row)
    #pragma unroll
    for (int rp = 0; rp < 4; rp++)
        #pragma unroll
        for (int c = 0; c < 4; c++) acc2[rp][c] = 0ull;

    for (int k0 = 0; k0 < F_IN; k0 += 16) {
        #pragma unroll
        for (int s = 0; s < 2; s++) {
            int f   = t + s * 256;
            int row = f >> 2;
            int seg = f & 3;
            int gr  = rowBase + row;
            float4 val = make_float4(0.f, 0.f, 0.f, 0.f);
            if (gr < n) val = *(const float4*)(x + (size_t)gr * F_IN + k0 + seg * 4);
            xs[seg * 4 + 0][row] = val.x;
            xs[seg * 4 + 1][row] = val.y;
            xs[seg * 4 + 2][row] = val.z;
            xs[seg * 4 + 3][row] = val.w;
        }
        {
            int col4 = t & 15;
            int kk   = t >> 4;
            float4 wv = *(const float4*)(W + (size_t)(k0 + kk) * F_OUT + col4 * 4);
            wv.x *= invs; wv.y *= invs; wv.z *= invs; wv.w *= invs;
            *(float4*)&ws[kk][col4 * 4] = wv;
        }
        __syncthreads();
        #pragma unroll
        for (int kk = 0; kk < 16; kk++) {
            // A row-pairs read directly as 64-bit words (8B-aligned, broadcast in-warp)
            const ull* ap64 = (const ull*)&xs[kk][ty * 8];
            ull ap0 = ap64[0];
            ull ap1 = ap64[1];
            ull ap2 = ap64[2];
            ull ap3 = ap64[3];
            float4 b  = *(const float4*)&ws[kk][tx * 4];
            ull bb0 = pack2(b.x, b.x);
            ull bb1 = pack2(b.y, b.y);
            ull bb2 = pack2(b.z, b.z);
            ull bb3 = pack2(b.w, b.w);
            acc2[0][0] = ffma2(ap0, bb0, acc2[0][0]);
            acc2[0][1] = ffma2(ap0, bb1, acc2[0][1]);
            acc2[0][2] = ffma2(ap0, bb2, acc2[0][2]);
            acc2[0][3] = ffma2(ap0, bb3, acc2[0][3]);
            acc2[1][0] = ffma2(ap1, bb0, acc2[1][0]);
            acc2[1][1] = ffma2(ap1, bb1, acc2[1][1]);
            acc2[1][2] = ffma2(ap1, bb2, acc2[1][2]);
            acc2[1][3] = ffma2(ap1, bb3, acc2[1][3]);
            acc2[2][0] = ffma2(ap2, bb0, acc2[2][0]);
            acc2[2][1] = ffma2(ap2, bb1, acc2[2][1]);
            acc2[2][2] = ffma2(ap2, bb2, acc2[2][2]);
            acc2[2][3] = ffma2(ap2, bb3, acc2[2][3]);
            acc2[3][0] = ffma2(ap3, bb0, acc2[3][0]);
            acc2[3][1] = ffma2(ap3, bb1, acc2[3][1]);
            acc2[3][2] = ffma2(ap3, bb2, acc2[3][2]);
            acc2[3][3] = ffma2(ap3, bb3, acc2[3][3]);
        }
        __syncthreads();
    }

    #pragma unroll
    for (int rp = 0; rp < 4; rp++) {
        float e0, o0, e1, o1, e2, o2, e3, o3;
        unpack2(acc2[rp][0], e0, o0);
        unpack2(acc2[rp][1], e1, o1);
        unpack2(acc2[rp][2], e2, o2);
        unpack2(acc2[rp][3], e3, o3);
        int gr0 = rowBase + ty * 8 + rp * 2;
        if (gr0 < n)
            *(float4*)(g_xp + (size_t)gr0 * F_OUT + tx * 4) = make_float4(e0, e1, e2, e3);
        if (gr0 + 1 < n)
            *(float4*)(g_xp + (size_t)(gr0 + 1) * F_OUT + tx * 4) = make_float4(o0, o1, o2, o3);
    }
}

// ------------- 4) aggregation: warp per node, 2 edge-streams x 16 lanes ---------
//   out[c] = sum_e rsqrt(deg[r])*w*rsqrt(deg[c]) * xp[r]  +  xp[c]/deg[c]  +  bias
__global__ __launch_bounds__(256) void k_agg(
    const float* __restrict__ bias, float* __restrict__ out, int n)
{
    int gt   = blockIdx.x * 256 + threadIdx.x;
    int node = gt >> 5;           // warp per node
    int lane = gt & 31;
    int eo   = lane >> 4;         // edge-stream: 0 or 1
    int l    = lane & 15;         // float4 lane within the 64-float row
    if (node >= n) return;        // uniform per warp

    float degc  = g_deg[node];
    float dis_c = rsqrtf(degc);
    int cnt = g_cur[node];
    if (cnt > CAP) cnt = CAP;
    const int2* bk = g_bkt + (size_t)node * CAP;

    float4 acc = make_float4(0.f, 0.f, 0.f, 0.f);
    for (int e = eo; e < cnt; e += 2) {
        int2  cu = bk[e];
        float ne = rsqrtf(g_deg[cu.x]) * __int_as_float(cu.y) * dis_c;
        float4 xv = *(const float4*)(g_xp + (size_t)cu.x * F_OUT + l * 4);
        acc.x += ne * xv.x;
        acc.y += ne * xv.y;
        acc.z += ne * xv.z;
        acc.w += ne * xv.w;
    }
    // combine the two edge-streams (lane <-> lane^16 hold the same feature chunk)
    acc.x += __shfl_xor_sync(0xffffffffu, acc.x, 16);
    acc.y += __shfl_xor_sync(0xffffffffu, acc.y, 16);
    acc.z += __shfl_xor_sync(0xffffffffu, acc.z, 16);
    acc.w += __shfl_xor_sync(0xffffffffu, acc.w, 16);

    if (eo == 0) {
        float invdeg = 1.0f / degc;
        float4 self = *(const float4*)(g_xp + (size_t)node * F_OUT + l * 4);
        float4 b4   = ((const float4*)bias)[l];
        float4 o;
        o.x = acc.x + self.x * invdeg + b4.x;
        o.y = acc.y + self.y * invdeg + b4.y;
        o.z = acc.z + self.z * invdeg + b4.z;
        o.w = acc.w + self.w * invdeg + b4.w;
        *(float4*)(out + (size_t)node * F_OUT + l * 4) = o;
    }
}

// ---------------------------------- launch --------------------------------------
extern "C" void kernel_launch(void* const* d_in, const int* in_sizes, int n_in,
                              void* d_out, int out_size) {
    const float* x    = (const float*)d_in[0];
    const int*   ei   = (const int*)d_in[1];    // int32 (JAX default, no x64)
    const float* W    = (const float*)d_in[2];
    const float* bias = (const float*)d_in[3];
    const float* ew   = (const float*)d_in[4];
    const float* u    = (const float*)d_in[5];
    float* out = (float*)d_out;

    int N = in_sizes[0] / F_IN;
    int E = in_sizes[4];

    k_sigma_init<<<(N + 255) / 256 + 1, 256>>>(W, u, N);
    k_edges<<<(E + 255) / 256, 256>>>(ew, ei, E);
    k_gemm<<<(N + 127) / 128, 256>>>(x, W, N);
    {
        long long total = (long long)N * 32;
        int blocks = (int)((total + 255) / 256);
        k_agg<<<blocks, 256>>>(bias, out, N);
    }
}